// round 2
// baseline (speedup 1.0000x reference)
#include <cuda_runtime.h>

// Problem constants
#define NB 8
#define NC 21
#define NW 512
#define NH 512
#define KK 5
#define KPAD 2
#define PLANE (NW * NH)

// Block: 128 threads, covers 2 adjacent rows (w0, w0+1), each thread owns
// 4 pixels in EACH row (same columns) => 8 pixels/thread, 1024 pixels/block.
// Grid: (NW/2, NB).
__global__ __launch_bounds__(128, 8)
void weight_matrix_kernel(const float* __restrict__ x,
                          const int*   __restrict__ y,
                          float*       __restrict__ out)
{
    // y tile: rows w0-2 .. w0+3 (6 rows), cols -2..513 stored at col+2.
    // Row stride 520 ints (2080B, 16B multiple) -> int4 LDS conflict-free.
    __shared__ int ytile[KK + 1][520];

    const int w0  = blockIdx.x * 2;
    const int b   = blockIdx.y;
    const int tid = threadIdx.x;
    const int h0  = tid * 4;

    // ---- stage 6 y rows into smem (coalesced) ----
    const int* yb = y + b * PLANE;
    #pragma unroll
    for (int r = 0; r < KK + 1; r++) {
        const int gr = w0 - KPAD + r;
        const bool rowok = (gr >= 0) && (gr < NW);
        const int* yrow = yb + gr * NH;
        for (int cc = tid; cc < 516; cc += 128) {
            const int gc = cc - KPAD;
            int v = 0;
            if (rowok && gc >= 0 && gc < NH) v = __ldg(&yrow[gc]);
            ytile[r][cc] = v;
        }
    }
    __syncthreads();

    // ---- argmax over 21 channels, 8 pixels (2 rows x float4) ----
    const float* xb = x + (size_t)(b * NC) * PLANE + w0 * NH + h0;
    float4 bu = *reinterpret_cast<const float4*>(xb);        // row w0
    float4 bv = *reinterpret_cast<const float4*>(xb + NH);   // row w0+1
    int bu0 = 0, bu1 = 0, bu2 = 0, bu3 = 0;
    int bv0 = 0, bv1 = 0, bv2 = 0, bv3 = 0;

    #pragma unroll 4
    for (int c = 1; c < NC; c++) {
        const float4 u = *reinterpret_cast<const float4*>(xb + c * PLANE);
        const float4 v = *reinterpret_cast<const float4*>(xb + c * PLANE + NH);
        if (u.x > bu.x) { bu.x = u.x; bu0 = c; }
        if (u.y > bu.y) { bu.y = u.y; bu1 = c; }
        if (u.z > bu.z) { bu.z = u.z; bu2 = c; }
        if (u.w > bu.w) { bu.w = u.w; bu3 = c; }
        if (v.x > bv.x) { bv.x = v.x; bv0 = c; }
        if (v.y > bv.y) { bv.y = v.y; bv1 = c; }
        if (v.z > bv.z) { bv.z = v.z; bv2 = c; }
        if (v.w > bv.w) { bv.w = v.w; bv3 = c; }
    }

    // ---- 5x5 mismatch counts. Tile rows 0..4 feed row w0, rows 1..5 feed
    //      row w0+1; each tile row is loaded from smem exactly once. ----
    int c0 = 0, c1 = 0, c2 = 0, c3 = 0;   // row w0
    int d0 = 0, d1 = 0, d2 = 0, d3 = 0;   // row w0+1

    #pragma unroll
    for (int r = 0; r < KK + 1; r++) {
        const int4 lo = *reinterpret_cast<const int4*>(&ytile[r][h0]);
        const int4 hi = *reinterpret_cast<const int4*>(&ytile[r][h0 + 4]);
        const int a0 = lo.x, a1 = lo.y, a2 = lo.z, a3 = lo.w;
        const int a4 = hi.x, a5 = hi.y, a6 = hi.z, a7 = hi.w;

        if (r < KK) {
            c0 += (a0 != bu0) + (a1 != bu0) + (a2 != bu0) + (a3 != bu0) + (a4 != bu0);
            c1 += (a1 != bu1) + (a2 != bu1) + (a3 != bu1) + (a4 != bu1) + (a5 != bu1);
            c2 += (a2 != bu2) + (a3 != bu2) + (a4 != bu2) + (a5 != bu2) + (a6 != bu2);
            c3 += (a3 != bu3) + (a4 != bu3) + (a5 != bu3) + (a6 != bu3) + (a7 != bu3);
        }
        if (r > 0) {
            d0 += (a0 != bv0) + (a1 != bv0) + (a2 != bv0) + (a3 != bv0) + (a4 != bv0);
            d1 += (a1 != bv1) + (a2 != bv1) + (a3 != bv1) + (a4 != bv1) + (a5 != bv1);
            d2 += (a2 != bv2) + (a3 != bv2) + (a4 != bv2) + (a5 != bv2) + (a6 != bv2);
            d3 += (a3 != bv3) + (a4 != bv3) + (a5 != bv3) + (a6 != bv3) + (a7 != bv3);
        }
    }

    float4 o0, o1;
    o0.x = 1.0f + 1.5f * (float)c0;
    o0.y = 1.0f + 1.5f * (float)c1;
    o0.z = 1.0f + 1.5f * (float)c2;
    o0.w = 1.0f + 1.5f * (float)c3;
    o1.x = 1.0f + 1.5f * (float)d0;
    o1.y = 1.0f + 1.5f * (float)d1;
    o1.z = 1.0f + 1.5f * (float)d2;
    o1.w = 1.0f + 1.5f * (float)d3;

    float* ob = out + (b * NW + w0) * NH + h0;
    *reinterpret_cast<float4*>(ob)      = o0;
    *reinterpret_cast<float4*>(ob + NH) = o1;
}

extern "C" void kernel_launch(void* const* d_in, const int* in_sizes, int n_in,
                              void* d_out, int out_size)
{
    const float* x = (const float*)d_in[0];
    const int*   y = (const int*)d_in[1];
    float*       o = (float*)d_out;

    dim3 grid(NW / 2, NB);
    weight_matrix_kernel<<<grid, 128>>>(x, y, o);
}

// round 3
// speedup vs baseline: 1.3384x; 1.3384x over previous
#include <cuda_runtime.h>

// Problem constants
#define NB 8
#define NC 21
#define NW 512
#define NH 512
#define KK 5
#define KPAD 2
#define PLANE (NW * NH)
#define RPB 4              // rows per block

// Block: 512 threads = 4 groups of 128; group s handles row w0+s, each thread
// 4 contiguous h-pixels (float4). Per-thread body identical to the known-good
// 40-reg R1 kernel. Grid: (NW/RPB, NB).
__global__ __launch_bounds__(512, 3)
void weight_matrix_kernel(const float* __restrict__ x,
                          const int*   __restrict__ y,
                          float*       __restrict__ out)
{
    // y tile: rows w0-2 .. w0+5 (8 rows), cols -2..513 stored at col+2.
    // Row stride 520 ints (2080B, 16B multiple) -> int4 LDS conflict-free.
    __shared__ int ytile[KK + RPB - 1][520];

    const int w0   = blockIdx.x * RPB;
    const int b    = blockIdx.y;
    const int tid  = threadIdx.x;
    const int s    = tid >> 7;          // 0..3: row group
    const int h0   = (tid & 127) * 4;   // pixel base column

    // ---- stage 8 y rows into smem (coalesced; zero pad out of range) ----
    const int* yb = y + b * PLANE;
    for (int idx = tid; idx < (KK + RPB - 1) * 520; idx += 512) {
        const int r  = idx / 520;
        const int cc = idx - r * 520;       // 0..519 (516..519 = pad zeros)
        const int gr = w0 - KPAD + r;
        const int gc = cc - KPAD;
        int v = 0;
        if (cc < 516 && gr >= 0 && gr < NW && gc >= 0 && gc < NH)
            v = __ldg(&yb[gr * NH + gc]);
        ytile[r][cc] = v;
    }
    __syncthreads();

    // ---- argmax over 21 channels for 4 pixels (strict > => first index) ----
    const int w = w0 + s;
    const float* xb = x + (size_t)(b * NC) * PLANE + w * NH + h0;
    float4 best = *reinterpret_cast<const float4*>(xb);
    int bc0 = 0, bc1 = 0, bc2 = 0, bc3 = 0;

    #pragma unroll 5
    for (int c = 1; c < NC; c++) {
        const float4 v = *reinterpret_cast<const float4*>(xb + c * PLANE);
        if (v.x > best.x) { best.x = v.x; bc0 = c; }
        if (v.y > best.y) { best.y = v.y; bc1 = c; }
        if (v.z > best.z) { best.z = v.z; bc2 = c; }
        if (v.w > best.w) { best.w = v.w; bc3 = c; }
    }

    // ---- 5x5 neighborhood mismatch count (tile rows s..s+4) ----
    int cnt0 = 0, cnt1 = 0, cnt2 = 0, cnt3 = 0;

    #pragma unroll
    for (int di = 0; di < KK; di++) {
        const int4 lo = *reinterpret_cast<const int4*>(&ytile[s + di][h0]);
        const int4 hi = *reinterpret_cast<const int4*>(&ytile[s + di][h0 + 4]);
        const int a0 = lo.x, a1 = lo.y, a2 = lo.z, a3 = lo.w;
        const int a4 = hi.x, a5 = hi.y, a6 = hi.z, a7 = hi.w;

        cnt0 += (a0 != bc0) + (a1 != bc0) + (a2 != bc0) + (a3 != bc0) + (a4 != bc0);
        cnt1 += (a1 != bc1) + (a2 != bc1) + (a3 != bc1) + (a4 != bc1) + (a5 != bc1);
        cnt2 += (a2 != bc2) + (a3 != bc2) + (a4 != bc2) + (a5 != bc2) + (a6 != bc2);
        cnt3 += (a3 != bc3) + (a4 != bc3) + (a5 != bc3) + (a6 != bc3) + (a7 != bc3);
    }

    float4 o;
    o.x = 1.0f + 1.5f * (float)cnt0;
    o.y = 1.0f + 1.5f * (float)cnt1;
    o.z = 1.0f + 1.5f * (float)cnt2;
    o.w = 1.0f + 1.5f * (float)cnt3;

    *reinterpret_cast<float4*>(out + (b * NW + w) * NH + h0) = o;
}

extern "C" void kernel_launch(void* const* d_in, const int* in_sizes, int n_in,
                              void* d_out, int out_size)
{
    const float* x = (const float*)d_in[0];
    const int*   y = (const int*)d_in[1];
    float*       o = (float*)d_out;

    dim3 grid(NW / RPB, NB);
    weight_matrix_kernel<<<grid, 512>>>(x, y, o);
}

// round 4
// speedup vs baseline: 1.4156x; 1.0576x over previous
#include <cuda_runtime.h>

// Problem constants
#define NB 8
#define NC 21
#define NW 512
#define NH 512
#define KK 5
#define KPAD 2
#define PLANE (NW * NH)
#define ROWW 130   // 32-bit words per tile row (520 bytes: cols -2..513 stored at +2, plus pad)

// Block: 128 threads, one row w, 4 contiguous h-pixels per thread (float4).
// Grid: (NW, NB). y-tile packed as bytes (labels 0..20 fit u8) -> 2.6KB smem.
__global__ __launch_bounds__(128, 10)
void weight_matrix_kernel(const float* __restrict__ x,
                          const int*   __restrict__ y,
                          float*       __restrict__ out)
{
    __shared__ unsigned int ytile[KK][ROWW];   // 2600 B

    const int w   = blockIdx.x;
    const int b   = blockIdx.y;
    const int tid = threadIdx.x;
    const int h0  = tid * 4;

    // ---- stage 5 y rows as packed bytes (zero padding like nn.Unfold) ----
    // word i of a row = stored cols 4i..4i+3 = global cols 4i-2..4i+1.
    // 4i-2 is even -> int2 global loads are 8B aligned.
    const int* yb = y + b * PLANE;
    #pragma unroll
    for (int k = 0; k < 6; k++) {              // 6*128 = 768 >= 5*130 = 650
        const int idx = tid + k * 128;
        if (idx < KK * ROWW) {
            const int r  = idx / ROWW;
            const int i  = idx - r * ROWW;
            const int gr = w - KPAD + r;
            unsigned int word = 0;
            if (gr >= 0 && gr < NW && i < 129) {
                const int* yrow = yb + gr * NH;
                const int c0 = 4 * i - 2;
                int2 a = make_int2(0, 0), bb = make_int2(0, 0);
                if (c0 >= 0)       a  = *reinterpret_cast<const int2*>(yrow + c0);
                if (c0 + 2 < NH)   bb = *reinterpret_cast<const int2*>(yrow + c0 + 2);
                word = (unsigned)(a.x & 0xff)
                     | ((unsigned)(a.y & 0xff) << 8)
                     | ((unsigned)(bb.x & 0xff) << 16)
                     | ((unsigned)bb.y << 24);
            }
            ytile[r][i] = word;
        }
    }
    __syncthreads();

    // ---- argmax over 21 channels for 4 pixels (strict > => first index) ----
    const float* xb = x + (size_t)(b * NC) * PLANE + w * NH + h0;
    float4 best = *reinterpret_cast<const float4*>(xb);
    int bc0 = 0, bc1 = 0, bc2 = 0, bc3 = 0;

    #pragma unroll 5
    for (int c = 1; c < NC; c++) {
        const float4 v = *reinterpret_cast<const float4*>(xb + c * PLANE);
        if (v.x > best.x) { best.x = v.x; bc0 = c; }
        if (v.y > best.y) { best.y = v.y; bc1 = c; }
        if (v.z > best.z) { best.z = v.z; bc2 = c; }
        if (v.w > best.w) { best.w = v.w; bc3 = c; }
    }

    // ---- 5x5 mismatch count, SIMD-in-word ----
    // Thread window = stored bytes [h0, h0+8) = words tid, tid+1 of each row.
    // Pixel p uses v0 bytes p..3 and v1 bytes 0..p (constant byte-position
    // masks, applied once at the end via dp4a). vsetne4 gives 0/1 per byte;
    // accumulators hold per-byte counts (max 5, no overflow).
    const unsigned int bcx0 = (unsigned)bc0 * 0x01010101u;
    const unsigned int bcx1 = (unsigned)bc1 * 0x01010101u;
    const unsigned int bcx2 = (unsigned)bc2 * 0x01010101u;
    const unsigned int bcx3 = (unsigned)bc3 * 0x01010101u;

    unsigned int a0 = 0, a1 = 0, a2 = 0, a3 = 0;   // from v0
    unsigned int e0 = 0, e1 = 0, e2 = 0, e3 = 0;   // from v1

    #pragma unroll
    for (int r = 0; r < KK; r++) {
        const unsigned int v0 = ytile[r][tid];
        const unsigned int v1 = ytile[r][tid + 1];
        a0 += __vsetne4(v0, bcx0);  e0 += __vsetne4(v1, bcx0);
        a1 += __vsetne4(v0, bcx1);  e1 += __vsetne4(v1, bcx1);
        a2 += __vsetne4(v0, bcx2);  e2 += __vsetne4(v1, bcx2);
        a3 += __vsetne4(v0, bcx3);  e3 += __vsetne4(v1, bcx3);
    }

    const int cnt0 = __dp4a(a0, 0x01010101u, __dp4a(e0, 0x00000001u, 0u));
    const int cnt1 = __dp4a(a1, 0x01010100u, __dp4a(e1, 0x00000101u, 0u));
    const int cnt2 = __dp4a(a2, 0x01010000u, __dp4a(e2, 0x00010101u, 0u));
    const int cnt3 = __dp4a(a3, 0x01000000u, __dp4a(e3, 0x01010101u, 0u));

    float4 o;
    o.x = 1.0f + 1.5f * (float)cnt0;
    o.y = 1.0f + 1.5f * (float)cnt1;
    o.z = 1.0f + 1.5f * (float)cnt2;
    o.w = 1.0f + 1.5f * (float)cnt3;

    *reinterpret_cast<float4*>(out + (b * NW + w) * NH + h0) = o;
}

extern "C" void kernel_launch(void* const* d_in, const int* in_sizes, int n_in,
                              void* d_out, int out_size)
{
    const float* x = (const float*)d_in[0];
    const int*   y = (const int*)d_in[1];
    float*       o = (float*)d_out;

    dim3 grid(NW, NB);
    weight_matrix_kernel<<<grid, 128>>>(x, y, o);
}